// round 12
// baseline (speedup 1.0000x reference)
#include <cuda_runtime.h>
#include <cuda_bf16.h>
#include <cuda_fp16.h>
#include <cstdint>

#define NN 50000
#define EE 800000
#define FIN 500
#define HH 96
#define NB 196        // scan blocks: ceil(NN/256)

// ---------------- scratch (device globals; no allocation allowed) ----------
__device__ int    g_deg_out[NN];
__device__ int    g_deg_in[NN];
__device__ int    g_iperm[NN];
__device__ int    g_off[NN + 1];
__device__ int    g_cur[NN];
__device__ int    g_bsum[NB];
__device__ int    g_boff[NB];
__device__ int    g_scan_sync[2];        // [0]=ticket, [1]=release flag
__device__ int    g_csr[EE];             // src per CSR slot
__device__ __half g_Y01[NN * 2 * HH];    // [norm_out*Y | norm_out*Y[perm]] per node
__device__ __half g_B0h[2 * NN * HH];    // layer-1 out, row n=2i+v, fp16
__device__ __half g_B2h[2 * NN * HH];    // B0 @ W2, row n=2i+v, fp16
__device__ float  g_wmsum[HH];
__device__ float  g_bmsum;
// transposed (n-major, k-contiguous), zero-padded, bf16 hi/lo weight copies
__device__ __nv_bfloat16 g_W1t_h[HH * 512];
__device__ __nv_bfloat16 g_W1t_l[HH * 512];
__device__ __nv_bfloat16 g_W2t_h[HH * 128];
__device__ __nv_bfloat16 g_W2t_l[HH * 128];

// ---------------- helpers ----------------------------------------------------
__device__ __forceinline__ uint32_t cvt2bf(float x, float y) {   // lo=x, hi=y
    uint32_t r;
    asm("cvt.rn.bf16x2.f32 %0, %1, %2;" : "=r"(r) : "f"(y), "f"(x));
    return r;
}

__device__ __forceinline__ void split_pair(float x, float y,
                                           uint32_t& hp, uint32_t& lp) {
    hp = cvt2bf(x, y);
    float fx = __uint_as_float(hp << 16);
    float fy = __uint_as_float(hp & 0xffff0000u);
    lp = cvt2bf(x - fx, y - fy);
}

// pair-position permutation: places (kq, kq+4) adjacent for LDS.64 reads
__device__ __forceinline__ int ppos(int kp) {
    int s = kp >> 3, w = kp & 7;
    return s * 8 + ((w < 4) ? 2 * w : 2 * (w - 4) + 1);
}

__device__ __forceinline__ void mma16816(float* c, uint32_t a0, uint32_t a1,
                                         uint32_t a2, uint32_t a3,
                                         uint32_t b0, uint32_t b1) {
    asm volatile(
        "mma.sync.aligned.m16n8k16.row.col.f32.bf16.bf16.f32 "
        "{%0,%1,%2,%3}, {%4,%5,%6,%7}, {%8,%9}, {%0,%1,%2,%3};"
        : "+f"(c[0]), "+f"(c[1]), "+f"(c[2]), "+f"(c[3])
        : "r"(a0), "r"(a1), "r"(a2), "r"(a3), "r"(b0), "r"(b1));
}

// 256-thread block inclusive scan
__device__ __forceinline__ int block_scan256(int v, int tid) {
    int lane = tid & 31, wid = tid >> 5;
    int inc = v;
    #pragma unroll
    for (int o = 1; o < 32; o <<= 1) {
        int u = __shfl_up_sync(0xffffffffu, inc, o);
        if (lane >= o) inc += u;
    }
    __shared__ int ws[8];
    if (lane == 31) ws[wid] = inc;
    __syncthreads();
    if (wid == 0) {
        int w = (lane < 8) ? ws[lane] : 0;
        #pragma unroll
        for (int o = 1; o < 8; o <<= 1) {
            int u = __shfl_up_sync(0xffffffffu, w, o);
            if (lane >= o) w += u;
        }
        if (lane < 8) ws[lane] = w;
    }
    __syncthreads();
    return inc + (wid ? ws[wid - 1] : 0);
}

// ---------------- setup kernels --------------------------------------------
__global__ void k_iperm(const int* __restrict__ perm) {
    int i = blockIdx.x * blockDim.x + threadIdx.x;
    if (i < NN) g_iperm[perm[i]] = i;
}

__global__ void k_count_out(const int* __restrict__ src) {
    int e = blockIdx.x * blockDim.x + threadIdx.x;
    if (e < EE) atomicAdd(&g_deg_out[src[e]], 1);
}

__global__ void k_count_in(const int* __restrict__ dst) {
    int e = blockIdx.x * blockDim.x + threadIdx.x;
    if (e < EE) atomicAdd(&g_deg_in[dst[e]], 1);
}

// single-launch chained scan of g_deg_in -> g_off/g_cur (exclusive)
__global__ void k_scan_fused() {
    int tid = threadIdx.x;
    int i = blockIdx.x * 256 + tid;
    int v = (i < NN) ? g_deg_in[i] : 0;
    int inc = block_scan256(v, tid);

    __shared__ bool last;
    if (tid == 255) {
        g_bsum[blockIdx.x] = inc;
        __threadfence();
        last = (atomicAdd(&g_scan_sync[0], 1) == NB - 1);
    }
    __syncthreads();

    if (last) {
        int bv = (tid < NB) ? g_bsum[tid] : 0;
        int binc = block_scan256(bv, tid);
        if (tid < NB) g_boff[tid] = binc - bv;
        if (tid == 0) {
            g_off[NN] = EE;
            __threadfence();
            *(volatile int*)&g_scan_sync[1] = 1;
        }
    }

    __shared__ int base;
    if (tid == 0) {
        while (*(volatile int*)&g_scan_sync[1] == 0) { }
        base = g_boff[blockIdx.x];
    }
    __syncthreads();
    int run = base + inc - v;
    if (i < NN) { g_off[i] = run; g_cur[i] = run; }
}

__global__ void k_scatter(const int* __restrict__ src, const int* __restrict__ dst) {
    int e = blockIdx.x * blockDim.x + threadIdx.x;
    if (e < EE) {
        int p = atomicAdd(&g_cur[dst[e]], 1);
        g_csr[p] = src[e];
    }
}

__global__ void k_wprep1(const float* __restrict__ W1) {
    int idx = blockIdx.x * blockDim.x + threadIdx.x;
    if (idx < HH * 512) {
        int j = idx >> 9, k = idx & 511;
        float v = (k < FIN) ? W1[k * HH + j] : 0.f;
        __nv_bfloat16 h = __float2bfloat16_rn(v);
        g_W1t_h[idx] = h;
        g_W1t_l[idx] = __float2bfloat16_rn(v - __bfloat162float(h));
    }
}

__global__ void k_wprep2(const float* __restrict__ W2,
                         const float* __restrict__ Wm, const float* __restrict__ bm) {
    int idx = blockIdx.x * blockDim.x + threadIdx.x;
    if (idx < HH * 128) {
        int j = idx >> 7, k = idx & 127;
        float v = (k < HH) ? W2[k * HH + j] : 0.f;
        __nv_bfloat16 h = __float2bfloat16_rn(v);
        g_W2t_h[idx] = h;
        g_W2t_l[idx] = __float2bfloat16_rn(v - __bfloat162float(h));
    }
    if (blockIdx.x == 0 && threadIdx.x < HH) {
        int k = threadIdx.x;
        float s = 0.f;
        for (int j = 0; j < HH; j++) s += Wm[k * HH + j];
        g_wmsum[k] = s;
        if (k == 0) {
            float sb = 0.f;
            for (int j = 0; j < HH; j++) sb += bm[j];
            g_bmsum = sb;
        }
    }
}

// ---------------- tensor-core GEMM via mma.sync, double-buffered ------------
// SMEM layout: row stride 24 words (conflict-free: qr*24 mod 32 in {0,24,16,8}),
// pair order permuted by ppos() so each MMA fragment is one aligned LDS.64.
#define AW 3072              // 128 * 24 words
#define BW 2304              // 96 * 24 words
#define GEMM_SMEM ((4 * AW + 4 * BW) * 4)   // 86016 bytes

template <int KCHUNKS, int KREAL, int LDA, int WLD, int NROWS, bool HALF_IN, bool EPI1>
__global__ void __launch_bounds__(256, 2)
k_gemm_mma(const void* __restrict__ Ain,
           const __nv_bfloat16* __restrict__ Wh,
           const __nv_bfloat16* __restrict__ Wl,
           __half* __restrict__ C) {
    extern __shared__ uint32_t dyn[];
    uint32_t* const AhB[2] = { dyn,            dyn + 2 * AW };
    uint32_t* const AlB[2] = { dyn + AW,       dyn + 3 * AW };
    uint32_t* const bbase  = dyn + 4 * AW;
    uint32_t* const BhB[2] = { bbase,          bbase + 2 * BW };
    uint32_t* const BlB[2] = { bbase + BW,     bbase + 3 * BW };

    int tid = threadIdx.x, wid = tid >> 5, lane = tid & 31;
    int mw = wid >> 1, nw = wid & 1;
    int r0 = blockIdx.x * 128;

    float acc[2][6][4];
    #pragma unroll
    for (int b = 0; b < 2; b++)
        #pragma unroll
        for (int t = 0; t < 6; t++)
            #pragma unroll
            for (int j = 0; j < 4; j++) acc[b][t][j] = 0.f;

    const int qr = lane >> 2, qc = lane & 3;

    float4   va4[4];
    float2   va2[8];
    uint32_t vbh[6], vbl[6];

    #define LOAD_CHUNK(cc)                                                     \
    {                                                                          \
        int kbase = (cc) * 32;                                                 \
        if (HALF_IN) {                                                         \
            int kvp = (KREAL - kbase) >> 1;                                    \
            if (kvp > 16) kvp = 16;                                            \
            _Pragma("unroll")                                                  \
            for (int it = 0; it < 8; it++) {                                   \
                int idx = tid + it * 256;                                      \
                int r = idx >> 4, kp = idx & 15;                               \
                int gr = r0 + r;                                               \
                float2 v = make_float2(0.f, 0.f);                              \
                if (gr < NROWS && kp < kvp) {                                  \
                    __half2 h2 = *(const __half2*)((const __half*)Ain +        \
                                   (size_t)gr * LDA + kbase + 2 * kp);         \
                    v = __half22float2(h2);                                    \
                }                                                              \
                va2[it] = v;                                                   \
            }                                                                  \
        } else {                                                               \
            int kvq = (KREAL - kbase + 3) >> 2;                                \
            if (kvq > 8) kvq = 8;                                              \
            _Pragma("unroll")                                                  \
            for (int it = 0; it < 4; it++) {                                   \
                int idx = tid + it * 256;                                      \
                int r = idx >> 3, q = idx & 7;                                 \
                int gr = r0 + r;                                               \
                float4 v = make_float4(0.f, 0.f, 0.f, 0.f);                    \
                if (gr < NROWS && q < kvq)                                     \
                    v = *(const float4*)((const float*)Ain +                   \
                            (size_t)gr * LDA + kbase + 4 * q);                 \
                va4[it] = v;                                                   \
            }                                                                  \
        }                                                                      \
        _Pragma("unroll")                                                      \
        for (int it = 0; it < 6; it++) {                                       \
            int idx = tid + it * 256;                                          \
            int n = idx >> 4, kp = idx & 15;                                   \
            vbh[it] = *(const uint32_t*)(Wh + (size_t)n * WLD + kbase + 2 * kp);\
            vbl[it] = *(const uint32_t*)(Wl + (size_t)n * WLD + kbase + 2 * kp);\
        }                                                                      \
    }

    #define STORE_CHUNK(buf)                                                   \
    {                                                                          \
        if (HALF_IN) {                                                         \
            _Pragma("unroll")                                                  \
            for (int it = 0; it < 8; it++) {                                   \
                int idx = tid + it * 256;                                      \
                int r = idx >> 4, kp = idx & 15;                               \
                uint32_t hp, lp;                                               \
                split_pair(va2[it].x, va2[it].y, hp, lp);                      \
                int pp = r * 24 + ppos(kp);                                    \
                AhB[buf][pp] = hp;                                             \
                AlB[buf][pp] = lp;                                             \
            }                                                                  \
        } else {                                                               \
            _Pragma("unroll")                                                  \
            for (int it = 0; it < 4; it++) {                                   \
                int idx = tid + it * 256;                                      \
                int r = idx >> 3, q = idx & 7;                                 \
                float4 v = va4[it];                                            \
                uint32_t h0, l0, h1, l1;                                       \
                split_pair(v.x, v.y, h0, l0);                                  \
                split_pair(v.z, v.w, h1, l1);                                  \
                int p0 = r * 24 + ppos(2 * q);                                 \
                int p1 = r * 24 + ppos(2 * q + 1);                             \
                AhB[buf][p0] = h0;                                             \
                AhB[buf][p1] = h1;                                             \
                AlB[buf][p0] = l0;                                             \
                AlB[buf][p1] = l1;                                             \
            }                                                                  \
        }                                                                      \
        _Pragma("unroll")                                                      \
        for (int it = 0; it < 6; it++) {                                       \
            int idx = tid + it * 256;                                          \
            int n = idx >> 4, kp = idx & 15;                                   \
            int pp = n * 24 + ppos(kp);                                        \
            BhB[buf][pp] = vbh[it];                                            \
            BlB[buf][pp] = vbl[it];                                            \
        }                                                                      \
    }

    LOAD_CHUNK(0);
    STORE_CHUNK(0);
    __syncthreads();

    for (int c = 0; c < KCHUNKS; c++) {
        if (c + 1 < KCHUNKS) LOAD_CHUNK(c + 1);

        const uint32_t* sAh = AhB[c & 1];
        const uint32_t* sAl = AlB[c & 1];
        const uint32_t* sBh = BhB[c & 1];
        const uint32_t* sBl = BlB[c & 1];

        #pragma unroll
        for (int s = 0; s < 2; s++) {
            int ko = s * 8 + 2 * qc;     // word offset within a row
            uint2 bh[6], bl[6];
            #pragma unroll
            for (int t = 0; t < 6; t++) {
                int bc = nw * 48 + t * 8 + qr;
                bh[t] = *(const uint2*)&sBh[bc * 24 + ko];
                bl[t] = *(const uint2*)&sBl[bc * 24 + ko];
            }
            #pragma unroll
            for (int b = 0; b < 2; b++) {
                int ar = mw * 32 + b * 16 + qr;
                uint2 ahL = *(const uint2*)&sAh[ar * 24 + ko];        // ah0, ah2
                uint2 ahH = *(const uint2*)&sAh[(ar + 8) * 24 + ko];  // ah1, ah3
                uint2 alL = *(const uint2*)&sAl[ar * 24 + ko];
                uint2 alH = *(const uint2*)&sAl[(ar + 8) * 24 + ko];
                #pragma unroll
                for (int t = 0; t < 6; t++) {
                    mma16816(acc[b][t], ahL.x, ahH.x, ahL.y, ahH.y, bh[t].x, bh[t].y);
                    mma16816(acc[b][t], ahL.x, ahH.x, ahL.y, ahH.y, bl[t].x, bl[t].y);
                    mma16816(acc[b][t], alL.x, alH.x, alL.y, alH.y, bh[t].x, bh[t].y);
                }
            }
        }

        if (c + 1 < KCHUNKS) {
            STORE_CHUNK((c + 1) & 1);
            __syncthreads();
        }
    }

    if (EPI1) {
        #pragma unroll
        for (int b = 0; b < 2; b++)
            #pragma unroll
            for (int h = 0; h < 2; h++) {
                int row = r0 + mw * 32 + b * 16 + qr + h * 8;
                if (row < NROWS) {
                    float no1 = rsqrtf((float)max(g_deg_out[row], 1));
                    int   n2  = g_iperm[row];
                    float no2 = rsqrtf((float)max(g_deg_out[n2], 1));
                    #pragma unroll
                    for (int t = 0; t < 6; t++) {
                        int col = nw * 48 + t * 8 + 2 * qc;
                        float vx = acc[b][t][2 * h], vy = acc[b][t][2 * h + 1];
                        *(__half2*)(g_Y01 + (size_t)row * (2 * HH) + col) =
                            __floats2half2_rn(no1 * vx, no1 * vy);
                        *(__half2*)(g_Y01 + (size_t)n2 * (2 * HH) + HH + col) =
                            __floats2half2_rn(no2 * vx, no2 * vy);
                    }
                }
            }
    } else {
        #pragma unroll
        for (int b = 0; b < 2; b++)
            #pragma unroll
            for (int t = 0; t < 6; t++) {
                int col = nw * 48 + t * 8 + 2 * qc;
                #pragma unroll
                for (int h = 0; h < 2; h++) {
                    int row = r0 + mw * 32 + b * 16 + qr + h * 8;
                    if (row < NROWS)
                        *(__half2*)(C + (size_t)row * HH + col) =
                            __floats2half2_rn(acc[b][t][2 * h], acc[b][t][2 * h + 1]);
                }
            }
    }
    #undef LOAD_CHUNK
    #undef STORE_CHUNK
}

// ---------------- SpMM gather core: 8x unrolled, 16B/lane -------------------
__device__ __forceinline__ void spmm_gather(const __half* __restrict__ base,
                                            size_t loff, int b, int e,
                                            float* acc) {
    #pragma unroll
    for (int t = 0; t < 8; t++) acc[t] = 0.f;
    auto addv = [&](uint4 v) {
        __half2* h2 = (__half2*)&v;
        #pragma unroll
        for (int t = 0; t < 4; t++) {
            float2 f = __half22float2(h2[t]);
            acc[2 * t]     += f.x;
            acc[2 * t + 1] += f.y;
        }
    };
    int p = b;
    for (; p + 8 <= e; p += 8) {
        int s[8];
        #pragma unroll
        for (int u = 0; u < 8; u++) s[u] = g_csr[p + u];
        uint4 v[8];
        #pragma unroll
        for (int u = 0; u < 8; u++)
            v[u] = *(const uint4*)(base + (size_t)s[u] * (2 * HH) + loff);
        #pragma unroll
        for (int u = 0; u < 8; u++) addv(v[u]);
    }
    for (; p + 2 <= e; p += 2) {
        int s0 = g_csr[p], s1 = g_csr[p + 1];
        uint4 v0 = *(const uint4*)(base + (size_t)s0 * (2 * HH) + loff);
        uint4 v1 = *(const uint4*)(base + (size_t)s1 * (2 * HH) + loff);
        addv(v0); addv(v1);
    }
    if (p < e)
        addv(*(const uint4*)(base + (size_t)g_csr[p] * (2 * HH) + loff));
}

// ---------------- fused SpMM layer 1: thread = (node, 24-chunk) -------------
__global__ void __launch_bounds__(384)
k_spmm1(const float* __restrict__ b1, const float* __restrict__ a1) {
    __shared__ float sb1[HH], sa1[HH];
    for (int j = threadIdx.x; j < HH; j += blockDim.x) {
        sb1[j] = b1[j];
        sa1[j] = a1[j];
    }
    __syncthreads();

    int nl = threadIdx.x / 24, c = threadIdx.x - nl * 24;
    int n = blockIdx.x * 16 + nl;
    if (n >= NN) return;
    int view = c / 12, chunk = c - view * 12;
    int b = g_off[n], e = g_off[n + 1];

    float acc[8];
    spmm_gather(g_Y01, (size_t)view * HH + chunk * 8, b, e, acc);

    float nin  = rsqrtf((float)max(g_deg_in[n], 1));
    float nout = rsqrtf((float)max(g_deg_out[n], 1));
    uint4 o;
    __half2* oh = (__half2*)&o;
    #pragma unroll
    for (int q = 0; q < 4; q++) {
        float r[2];
        #pragma unroll
        for (int u = 0; u < 2; u++) {
            int j = chunk * 8 + 2 * q + u;
            float h = fmaf(acc[2 * q + u], nin, sb1[j]);
            h = (h >= 0.f) ? h : sa1[j] * h;
            r[u] = nout * h;
        }
        oh[q] = __floats2half2_rn(r[0], r[1]);
    }
    *(uint4*)(g_B0h + ((size_t)(2 * n + view)) * HH + chunk * 8) = o;
}

// ---------------- fused SpMM layer 2 + readout: 24-thread groups ------------
__global__ void __launch_bounds__(384)
k_spmm2(const float* __restrict__ b2, const float* __restrict__ a2,
        float* __restrict__ out) {
    __shared__ float sb2[HH], sa2[HH], swm[HH], sp[384];
    for (int j = threadIdx.x; j < HH; j += blockDim.x) {
        sb2[j] = b2[j];
        sa2[j] = a2[j];
        swm[j] = g_wmsum[j];
    }
    __syncthreads();

    int nl = threadIdx.x / 24, c = threadIdx.x - nl * 24;
    int n = blockIdx.x * 16 + nl;
    int view = c / 12, chunk = c - view * 12;

    float part = 0.f;
    if (n < NN) {
        int b = g_off[n], e = g_off[n + 1];
        float acc[8];
        spmm_gather(g_B2h, (size_t)view * HH + chunk * 8, b, e, acc);
        float nin = rsqrtf((float)max(g_deg_in[n], 1));
        #pragma unroll
        for (int t = 0; t < 8; t++) {
            int j = chunk * 8 + t;
            float h = fmaf(acc[t], nin, sb2[j]);
            h = (h >= 0.f) ? h : sa2[j] * h;
            part = fmaf(h, swm[j], part);
        }
    }
    sp[threadIdx.x] = part;
    __syncthreads();

    if (threadIdx.x < 32) {
        int nl2 = threadIdx.x >> 1, vw = threadIdx.x & 1;
        int n2 = blockIdx.x * 16 + nl2;
        if (n2 < NN) {
            float s = g_bmsum;
            #pragma unroll
            for (int k = 0; k < 12; k++) s += sp[nl2 * 24 + vw * 12 + k];
            out[(size_t)vw * NN + n2] = s;
        }
    }
}

// ---------------- launch ----------------------------------------------------
extern "C" void kernel_launch(void* const* d_in, const int* in_sizes, int n_in,
                              void* d_out, int out_size) {
    const float* x    = (const float*)d_in[0];
    const int*   src  = (const int*)  d_in[1];
    const int*   dst  = (const int*)  d_in[2];
    const int*   perm = (const int*)  d_in[3];
    const float* W1   = (const float*)d_in[4];
    const float* b1   = (const float*)d_in[5];
    const float* a1   = (const float*)d_in[6];
    const float* W2   = (const float*)d_in[7];
    const float* b2   = (const float*)d_in[8];
    const float* a2   = (const float*)d_in[9];
    const float* Wm   = (const float*)d_in[10];
    const float* bm   = (const float*)d_in[11];
    float* out = (float*)d_out;

    __half *pB0h, *pB2h;
    __nv_bfloat16 *pW1h, *pW1l, *pW2h, *pW2l;
    int *pDegOut, *pDegIn, *pSync;
    cudaGetSymbolAddress((void**)&pB0h, g_B0h);
    cudaGetSymbolAddress((void**)&pB2h, g_B2h);
    cudaGetSymbolAddress((void**)&pW1h, g_W1t_h);
    cudaGetSymbolAddress((void**)&pW1l, g_W1t_l);
    cudaGetSymbolAddress((void**)&pW2h, g_W2t_h);
    cudaGetSymbolAddress((void**)&pW2l, g_W2t_l);
    cudaGetSymbolAddress((void**)&pDegOut, g_deg_out);
    cudaGetSymbolAddress((void**)&pDegIn,  g_deg_in);
    cudaGetSymbolAddress((void**)&pSync,   g_scan_sync);

    static cudaStream_t sB = nullptr, sC = nullptr, sD = nullptr;
    static cudaEvent_t evF, evDeg, evY, evCSR, evW2, evT;
    if (!sB) {
        cudaStreamCreateWithFlags(&sB, cudaStreamNonBlocking);
        cudaStreamCreateWithFlags(&sC, cudaStreamNonBlocking);
        cudaStreamCreateWithFlags(&sD, cudaStreamNonBlocking);
        cudaEventCreateWithFlags(&evF,   cudaEventDisableTiming);
        cudaEventCreateWithFlags(&evDeg, cudaEventDisableTiming);
        cudaEventCreateWithFlags(&evY,   cudaEventDisableTiming);
        cudaEventCreateWithFlags(&evCSR, cudaEventDisableTiming);
        cudaEventCreateWithFlags(&evW2,  cudaEventDisableTiming);
        cudaEventCreateWithFlags(&evT,   cudaEventDisableTiming);
        cudaFuncSetAttribute(k_gemm_mma<16, FIN, FIN, 512, NN, false, true>,
                             cudaFuncAttributeMaxDynamicSharedMemorySize, GEMM_SMEM);
        cudaFuncSetAttribute(k_gemm_mma<3, HH, HH, 128, 2 * NN, true, false>,
                             cudaFuncAttributeMaxDynamicSharedMemorySize, GEMM_SMEM);
    }

    const int GN  = (NN + 255) / 256;
    const int GE  = (EE + 255) / 256;
    const int GS  = (NN + 15) / 16;
    const int GT1 = (NN + 127) / 128;
    const int GT2 = (2 * NN + 127) / 128;

    // fork
    cudaEventRecord(evF, 0);
    cudaStreamWaitEvent(sB, evF, 0);
    cudaStreamWaitEvent(sC, evF, 0);
    cudaStreamWaitEvent(sD, evF, 0);

    // memsets
    cudaMemsetAsync(pDegIn,  0, NN * sizeof(int), sB);
    cudaMemsetAsync(pSync,   0, 2 * sizeof(int),  sB);
    cudaMemsetAsync(pDegOut, 0, NN * sizeof(int), sC);

    // kernel #1: W1 prep (main)
    k_wprep1<<<(HH * 512 + 255) / 256, 256>>>(W1);
    // kernels #2-3: iperm + count_out (sC)
    k_iperm<<<GN, 256, 0, sC>>>(perm);
    k_count_out<<<GE, 256, 0, sC>>>(src);
    cudaEventRecord(evDeg, sC);

    // kernel #4: GEMM1 (main) -- profiled launch
    cudaStreamWaitEvent(0, evDeg, 0);
    k_gemm_mma<16, FIN, FIN, 512, NN, false, true>
        <<<GT1, 256, GEMM_SMEM>>>(x, pW1h, pW1l, pB0h /*unused*/);
    cudaEventRecord(evY, 0);

    // kernels #5-7: CSR build (sB)
    k_count_in<<<GE, 256, 0, sB>>>(dst);
    k_scan_fused<<<NB, 256, 0, sB>>>();
    k_scatter<<<GE, 256, 0, sB>>>(src, dst);
    cudaEventRecord(evCSR, sB);

    // kernel #8: W2 prep + wmsum (sC, hidden)
    k_wprep2<<<(HH * 128 + 255) / 256, 256, 0, sC>>>(W2, Wm, bm);
    cudaEventRecord(evW2, sC);

    // kernels #9-10: spmm1 -> GEMM2 (sD)
    cudaStreamWaitEvent(sD, evY, 0);
    cudaStreamWaitEvent(sD, evCSR, 0);
    k_spmm1<<<GS, 384, 0, sD>>>(b1, a1);
    cudaStreamWaitEvent(sD, evW2, 0);
    k_gemm_mma<3, HH, HH, 128, 2 * NN, true, false>
        <<<GT2, 256, GEMM_SMEM, sD>>>(pB0h, pW2h, pW2l, pB2h);
    cudaEventRecord(evT, sD);

    // kernel #11: spmm2 (main = capture stream, graph leaf)
    cudaStreamWaitEvent(0, evT, 0);
    k_spmm2<<<GS, 384>>>(b2, a2, out);
}

// round 14
// speedup vs baseline: 1.0484x; 1.0484x over previous
#include <cuda_runtime.h>
#include <cuda_bf16.h>
#include <cuda_fp16.h>
#include <cstdint>

#define NN 50000
#define EE 800000
#define FIN 500
#define HH 96
#define NB 196        // scan blocks: ceil(NN/256)

// ---------------- scratch (device globals; no allocation allowed) ----------
__device__ int    g_deg_out[NN];
__device__ int    g_deg_in[NN];
__device__ int    g_iperm[NN];
__device__ int    g_off[NN + 1];
__device__ int    g_cur[NN];
__device__ int    g_bsum[NB];
__device__ int    g_boff[NB];
__device__ int    g_scan_sync[2];        // [0]=ticket, [1]=release flag
__device__ int    g_csr[EE];             // src per CSR slot
__device__ __half g_Y01[NN * 2 * HH];    // [norm_out*Y | norm_out*Y[perm]] per node
__device__ __half g_B0h[2 * NN * HH];    // layer-1 out, row n=2i+v, fp16
__device__ __half g_B2h[2 * NN * HH];    // B0 @ W2, row n=2i+v, fp16
__device__ float  g_wmsum[HH];
__device__ float  g_bmsum;
// transposed (n-major, k-contiguous), zero-padded, bf16 hi/lo weight copies
__device__ __nv_bfloat16 g_W1t_h[HH * 512];
__device__ __nv_bfloat16 g_W1t_l[HH * 512];
__device__ __nv_bfloat16 g_W2t_h[HH * 128];
__device__ __nv_bfloat16 g_W2t_l[HH * 128];

// ---------------- helpers ----------------------------------------------------
__device__ __forceinline__ uint32_t cvt2bf(float x, float y) {   // lo=x, hi=y
    uint32_t r;
    asm("cvt.rn.bf16x2.f32 %0, %1, %2;" : "=r"(r) : "f"(y), "f"(x));
    return r;
}

__device__ __forceinline__ void split_pair(float x, float y,
                                           uint32_t& hp, uint32_t& lp) {
    hp = cvt2bf(x, y);
    float fx = __uint_as_float(hp << 16);
    float fy = __uint_as_float(hp & 0xffff0000u);
    lp = cvt2bf(x - fx, y - fy);
}

__device__ __forceinline__ void mma16816(float* c, uint32_t a0, uint32_t a1,
                                         uint32_t a2, uint32_t a3,
                                         uint32_t b0, uint32_t b1) {
    asm volatile(
        "mma.sync.aligned.m16n8k16.row.col.f32.bf16.bf16.f32 "
        "{%0,%1,%2,%3}, {%4,%5,%6,%7}, {%8,%9}, {%0,%1,%2,%3};"
        : "+f"(c[0]), "+f"(c[1]), "+f"(c[2]), "+f"(c[3])
        : "r"(a0), "r"(a1), "r"(a2), "r"(a3), "r"(b0), "r"(b1));
}

// 256-thread block inclusive scan
__device__ __forceinline__ int block_scan256(int v, int tid) {
    int lane = tid & 31, wid = tid >> 5;
    int inc = v;
    #pragma unroll
    for (int o = 1; o < 32; o <<= 1) {
        int u = __shfl_up_sync(0xffffffffu, inc, o);
        if (lane >= o) inc += u;
    }
    __shared__ int ws[8];
    if (lane == 31) ws[wid] = inc;
    __syncthreads();
    if (wid == 0) {
        int w = (lane < 8) ? ws[lane] : 0;
        #pragma unroll
        for (int o = 1; o < 8; o <<= 1) {
            int u = __shfl_up_sync(0xffffffffu, w, o);
            if (lane >= o) w += u;
        }
        if (lane < 8) ws[lane] = w;
    }
    __syncthreads();
    return inc + (wid ? ws[wid - 1] : 0);
}

// ---------------- setup kernels --------------------------------------------
__global__ void k_iperm(const int* __restrict__ perm) {
    int i = blockIdx.x * blockDim.x + threadIdx.x;
    if (i < NN) g_iperm[perm[i]] = i;
}

__global__ void k_count_out(const int* __restrict__ src) {
    int e = blockIdx.x * blockDim.x + threadIdx.x;
    if (e < EE) atomicAdd(&g_deg_out[src[e]], 1);
}

__global__ void k_count_in(const int* __restrict__ dst) {
    int e = blockIdx.x * blockDim.x + threadIdx.x;
    if (e < EE) atomicAdd(&g_deg_in[dst[e]], 1);
}

// single-launch chained scan of g_deg_in -> g_off/g_cur (exclusive)
__global__ void k_scan_fused() {
    int tid = threadIdx.x;
    int i = blockIdx.x * 256 + tid;
    int v = (i < NN) ? g_deg_in[i] : 0;
    int inc = block_scan256(v, tid);

    __shared__ bool last;
    if (tid == 255) {
        g_bsum[blockIdx.x] = inc;
        __threadfence();
        last = (atomicAdd(&g_scan_sync[0], 1) == NB - 1);
    }
    __syncthreads();

    if (last) {
        int bv = (tid < NB) ? g_bsum[tid] : 0;
        int binc = block_scan256(bv, tid);
        if (tid < NB) g_boff[tid] = binc - bv;
        if (tid == 0) {
            g_off[NN] = EE;
            __threadfence();
            *(volatile int*)&g_scan_sync[1] = 1;
        }
    }

    __shared__ int base;
    if (tid == 0) {
        while (*(volatile int*)&g_scan_sync[1] == 0) { }
        base = g_boff[blockIdx.x];
    }
    __syncthreads();
    int run = base + inc - v;
    if (i < NN) { g_off[i] = run; g_cur[i] = run; }
}

__global__ void k_scatter(const int* __restrict__ src, const int* __restrict__ dst) {
    int e = blockIdx.x * blockDim.x + threadIdx.x;
    if (e < EE) {
        int p = atomicAdd(&g_cur[dst[e]], 1);
        g_csr[p] = src[e];
    }
}

__global__ void k_wprep1(const float* __restrict__ W1) {
    int idx = blockIdx.x * blockDim.x + threadIdx.x;
    if (idx < HH * 512) {
        int j = idx >> 9, k = idx & 511;
        float v = (k < FIN) ? W1[k * HH + j] : 0.f;
        __nv_bfloat16 h = __float2bfloat16_rn(v);
        g_W1t_h[idx] = h;
        g_W1t_l[idx] = __float2bfloat16_rn(v - __bfloat162float(h));
    }
}

__global__ void k_wprep2(const float* __restrict__ W2,
                         const float* __restrict__ Wm, const float* __restrict__ bm) {
    int idx = blockIdx.x * blockDim.x + threadIdx.x;
    if (idx < HH * 128) {
        int j = idx >> 7, k = idx & 127;
        float v = (k < HH) ? W2[k * HH + j] : 0.f;
        __nv_bfloat16 h = __float2bfloat16_rn(v);
        g_W2t_h[idx] = h;
        g_W2t_l[idx] = __float2bfloat16_rn(v - __bfloat162float(h));
    }
    if (blockIdx.x == 0 && threadIdx.x < HH) {
        int k = threadIdx.x;
        float s = 0.f;
        for (int j = 0; j < HH; j++) s += Wm[k * HH + j];
        g_wmsum[k] = s;
        if (k == 0) {
            float sb = 0.f;
            for (int j = 0; j < HH; j++) sb += bm[j];
            g_bmsum = sb;
        }
    }
}

// ---------------- tensor-core GEMM via mma.sync, double-buffered ------------
// CTA: 128 rows x 96 cols, 8 warps as 4(m) x 2(n); warp = 2 m16 bands x 6 n8.
// K chunks of 32 (2 x k16). bf16 hi/lo 3-pass, issued PASS-OUTER so
// consecutive HMMAs hit independent accumulators (12-deep reuse distance).
#define AB_U32 2176              // 128*17
#define BB_U32 1632              // 96*17
#define GEMM_SMEM ((4 * AB_U32 + 4 * BB_U32) * 4)   // 60928 bytes

template <int KCHUNKS, int KREAL, int LDA, int WLD, int NROWS, bool HALF_IN, bool EPI1>
__global__ void __launch_bounds__(256, 2)
k_gemm_mma(const void* __restrict__ Ain,
           const __nv_bfloat16* __restrict__ Wh,
           const __nv_bfloat16* __restrict__ Wl,
           __half* __restrict__ C) {
    extern __shared__ uint32_t dyn[];
    uint32_t* const AhB[2] = { dyn,               dyn + 2 * AB_U32 };
    uint32_t* const AlB[2] = { dyn + AB_U32,      dyn + 3 * AB_U32 };
    uint32_t* const bbase  = dyn + 4 * AB_U32;
    uint32_t* const BhB[2] = { bbase,             bbase + 2 * BB_U32 };
    uint32_t* const BlB[2] = { bbase + BB_U32,    bbase + 3 * BB_U32 };

    int tid = threadIdx.x, wid = tid >> 5, lane = tid & 31;
    int mw = wid >> 1, nw = wid & 1;
    int r0 = blockIdx.x * 128;

    float acc[2][6][4];
    #pragma unroll
    for (int b = 0; b < 2; b++)
        #pragma unroll
        for (int t = 0; t < 6; t++)
            #pragma unroll
            for (int j = 0; j < 4; j++) acc[b][t][j] = 0.f;

    const int qr = lane >> 2, qc = lane & 3;

    float4   va4[4];
    float2   va2[8];
    uint32_t vbh[6], vbl[6];

    #define LOAD_CHUNK(cc)                                                     \
    {                                                                          \
        int kbase = (cc) * 32;                                                 \
        if (HALF_IN) {                                                         \
            int kvp = (KREAL - kbase) >> 1;                                    \
            if (kvp > 16) kvp = 16;                                            \
            _Pragma("unroll")                                                  \
            for (int it = 0; it < 8; it++) {                                   \
                int idx = tid + it * 256;                                      \
                int r = idx >> 4, kp = idx & 15;                               \
                int gr = r0 + r;                                               \
                float2 v = make_float2(0.f, 0.f);                              \
                if (gr < NROWS && kp < kvp) {                                  \
                    __half2 h2 = *(const __half2*)((const __half*)Ain +        \
                                   (size_t)gr * LDA + kbase + 2 * kp);         \
                    v = __half22float2(h2);                                    \
                }                                                              \
                va2[it] = v;                                                   \
            }                                                                  \
        } else {                                                               \
            int kvq = (KREAL - kbase + 3) >> 2;                                \
            if (kvq > 8) kvq = 8;                                              \
            _Pragma("unroll")                                                  \
            for (int it = 0; it < 4; it++) {                                   \
                int idx = tid + it * 256;                                      \
                int r = idx >> 3, q = idx & 7;                                 \
                int gr = r0 + r;                                               \
                float4 v = make_float4(0.f, 0.f, 0.f, 0.f);                    \
                if (gr < NROWS && q < kvq)                                     \
                    v = *(const float4*)((const float*)Ain +                   \
                            (size_t)gr * LDA + kbase + 4 * q);                 \
                va4[it] = v;                                                   \
            }                                                                  \
        }                                                                      \
        _Pragma("unroll")                                                      \
        for (int it = 0; it < 6; it++) {                                       \
            int idx = tid + it * 256;                                          \
            int n = idx >> 4, kp = idx & 15;                                   \
            vbh[it] = *(const uint32_t*)(Wh + (size_t)n * WLD + kbase + 2 * kp);\
            vbl[it] = *(const uint32_t*)(Wl + (size_t)n * WLD + kbase + 2 * kp);\
        }                                                                      \
    }

    #define STORE_CHUNK(buf)                                                   \
    {                                                                          \
        if (HALF_IN) {                                                         \
            _Pragma("unroll")                                                  \
            for (int it = 0; it < 8; it++) {                                   \
                int idx = tid + it * 256;                                      \
                int r = idx >> 4, kp = idx & 15;                               \
                uint32_t hp, lp;                                               \
                split_pair(va2[it].x, va2[it].y, hp, lp);                      \
                AhB[buf][r * 17 + kp] = hp;                                    \
                AlB[buf][r * 17 + kp] = lp;                                    \
            }                                                                  \
        } else {                                                               \
            _Pragma("unroll")                                                  \
            for (int it = 0; it < 4; it++) {                                   \
                int idx = tid + it * 256;                                      \
                int r = idx >> 3, q = idx & 7;                                 \
                float4 v = va4[it];                                            \
                uint32_t h0, l0, h1, l1;                                       \
                split_pair(v.x, v.y, h0, l0);                                  \
                split_pair(v.z, v.w, h1, l1);                                  \
                AhB[buf][r * 17 + 2 * q]     = h0;                             \
                AhB[buf][r * 17 + 2 * q + 1] = h1;                             \
                AlB[buf][r * 17 + 2 * q]     = l0;                             \
                AlB[buf][r * 17 + 2 * q + 1] = l1;                             \
            }                                                                  \
        }                                                                      \
        _Pragma("unroll")                                                      \
        for (int it = 0; it < 6; it++) {                                       \
            int idx = tid + it * 256;                                          \
            int n = idx >> 4, kp = idx & 15;                                   \
            BhB[buf][n * 17 + kp] = vbh[it];                                   \
            BlB[buf][n * 17 + kp] = vbl[it];                                   \
        }                                                                      \
    }

    LOAD_CHUNK(0);
    STORE_CHUNK(0);
    __syncthreads();

    for (int c = 0; c < KCHUNKS; c++) {
        if (c + 1 < KCHUNKS) LOAD_CHUNK(c + 1);

        const uint32_t* sAh = AhB[c & 1];
        const uint32_t* sAl = AlB[c & 1];
        const uint32_t* sBh = BhB[c & 1];
        const uint32_t* sBl = BlB[c & 1];

        #pragma unroll
        for (int s = 0; s < 2; s++) {
            int kq = s * 8 + qc;
            uint32_t bh[6][2], bl[6][2];
            #pragma unroll
            for (int t = 0; t < 6; t++) {
                int bc = nw * 48 + t * 8 + qr;
                bh[t][0] = sBh[bc * 17 + kq]; bh[t][1] = sBh[bc * 17 + kq + 4];
                bl[t][0] = sBl[bc * 17 + kq]; bl[t][1] = sBl[bc * 17 + kq + 4];
            }
            uint32_t ah[2][4], al[2][4];
            #pragma unroll
            for (int b = 0; b < 2; b++) {
                int ar = mw * 32 + b * 16 + qr;
                ah[b][0] = sAh[ar * 17 + kq];     ah[b][1] = sAh[(ar + 8) * 17 + kq];
                ah[b][2] = sAh[ar * 17 + kq + 4]; ah[b][3] = sAh[(ar + 8) * 17 + kq + 4];
                al[b][0] = sAl[ar * 17 + kq];     al[b][1] = sAl[(ar + 8) * 17 + kq];
                al[b][2] = sAl[ar * 17 + kq + 4]; al[b][3] = sAl[(ar + 8) * 17 + kq + 4];
            }
            // pass-outer issue order: consecutive HMMAs hit independent accs
            #pragma unroll
            for (int p = 0; p < 3; p++) {
                #pragma unroll
                for (int b = 0; b < 2; b++) {
                    const uint32_t* a = (p == 2) ? al[b] : ah[b];
                    #pragma unroll
                    for (int t = 0; t < 6; t++) {
                        const uint32_t* bb = (p == 1) ? bl[t] : bh[t];
                        mma16816(acc[b][t], a[0], a[1], a[2], a[3], bb[0], bb[1]);
                    }
                }
            }
        }

        if (c + 1 < KCHUNKS) {
            STORE_CHUNK((c + 1) & 1);
            __syncthreads();
        }
    }

    if (EPI1) {
        #pragma unroll
        for (int b = 0; b < 2; b++)
            #pragma unroll
            for (int h = 0; h < 2; h++) {
                int row = r0 + mw * 32 + b * 16 + qr + h * 8;
                if (row < NROWS) {
                    float no1 = rsqrtf((float)max(g_deg_out[row], 1));
                    int   n2  = g_iperm[row];
                    float no2 = rsqrtf((float)max(g_deg_out[n2], 1));
                    #pragma unroll
                    for (int t = 0; t < 6; t++) {
                        int col = nw * 48 + t * 8 + 2 * qc;
                        float vx = acc[b][t][2 * h], vy = acc[b][t][2 * h + 1];
                        *(__half2*)(g_Y01 + (size_t)row * (2 * HH) + col) =
                            __floats2half2_rn(no1 * vx, no1 * vy);
                        *(__half2*)(g_Y01 + (size_t)n2 * (2 * HH) + HH + col) =
                            __floats2half2_rn(no2 * vx, no2 * vy);
                    }
                }
            }
    } else {
        #pragma unroll
        for (int b = 0; b < 2; b++)
            #pragma unroll
            for (int t = 0; t < 6; t++) {
                int col = nw * 48 + t * 8 + 2 * qc;
                #pragma unroll
                for (int h = 0; h < 2; h++) {
                    int row = r0 + mw * 32 + b * 16 + qr + h * 8;
                    if (row < NROWS)
                        *(__half2*)(C + (size_t)row * HH + col) =
                            __floats2half2_rn(acc[b][t][2 * h], acc[b][t][2 * h + 1]);
                }
            }
    }
    #undef LOAD_CHUNK
    #undef STORE_CHUNK
}

// ---------------- SpMM gather core: 8x unrolled, 16B/lane -------------------
__device__ __forceinline__ void spmm_gather(const __half* __restrict__ base,
                                            size_t loff, int b, int e,
                                            float* acc) {
    #pragma unroll
    for (int t = 0; t < 8; t++) acc[t] = 0.f;
    auto addv = [&](uint4 v) {
        __half2* h2 = (__half2*)&v;
        #pragma unroll
        for (int t = 0; t < 4; t++) {
            float2 f = __half22float2(h2[t]);
            acc[2 * t]     += f.x;
            acc[2 * t + 1] += f.y;
        }
    };
    int p = b;
    for (; p + 8 <= e; p += 8) {
        int s[8];
        #pragma unroll
        for (int u = 0; u < 8; u++) s[u] = g_csr[p + u];
        uint4 v[8];
        #pragma unroll
        for (int u = 0; u < 8; u++)
            v[u] = *(const uint4*)(base + (size_t)s[u] * (2 * HH) + loff);
        #pragma unroll
        for (int u = 0; u < 8; u++) addv(v[u]);
    }
    for (; p + 2 <= e; p += 2) {
        int s0 = g_csr[p], s1 = g_csr[p + 1];
        uint4 v0 = *(const uint4*)(base + (size_t)s0 * (2 * HH) + loff);
        uint4 v1 = *(const uint4*)(base + (size_t)s1 * (2 * HH) + loff);
        addv(v0); addv(v1);
    }
    if (p < e)
        addv(*(const uint4*)(base + (size_t)g_csr[p] * (2 * HH) + loff));
}

// ---------------- fused SpMM layer 1: thread = (node, 24-chunk) -------------
__global__ void __launch_bounds__(384)
k_spmm1(const float* __restrict__ b1, const float* __restrict__ a1) {
    __shared__ float sb1[HH], sa1[HH];
    for (int j = threadIdx.x; j < HH; j += blockDim.x) {
        sb1[j] = b1[j];
        sa1[j] = a1[j];
    }
    __syncthreads();

    int nl = threadIdx.x / 24, c = threadIdx.x - nl * 24;
    int n = blockIdx.x * 16 + nl;
    if (n >= NN) return;
    int view = c / 12, chunk = c - view * 12;
    int b = g_off[n], e = g_off[n + 1];

    float acc[8];
    spmm_gather(g_Y01, (size_t)view * HH + chunk * 8, b, e, acc);

    float nin  = rsqrtf((float)max(g_deg_in[n], 1));
    float nout = rsqrtf((float)max(g_deg_out[n], 1));
    uint4 o;
    __half2* oh = (__half2*)&o;
    #pragma unroll
    for (int q = 0; q < 4; q++) {
        float r[2];
        #pragma unroll
        for (int u = 0; u < 2; u++) {
            int j = chunk * 8 + 2 * q + u;
            float h = fmaf(acc[2 * q + u], nin, sb1[j]);
            h = (h >= 0.f) ? h : sa1[j] * h;
            r[u] = nout * h;
        }
        oh[q] = __floats2half2_rn(r[0], r[1]);
    }
    *(uint4*)(g_B0h + ((size_t)(2 * n + view)) * HH + chunk * 8) = o;
}

// ---------------- fused SpMM layer 2 + readout: 24-thread groups ------------
__global__ void __launch_bounds__(384)
k_spmm2(const float* __restrict__ b2, const float* __restrict__ a2,
        float* __restrict__ out) {
    __shared__ float sb2[HH], sa2[HH], swm[HH], sp[384];
    for (int j = threadIdx.x; j < HH; j += blockDim.x) {
        sb2[j] = b2[j];
        sa2[j] = a2[j];
        swm[j] = g_wmsum[j];
    }
    __syncthreads();

    int nl = threadIdx.x / 24, c = threadIdx.x - nl * 24;
    int n = blockIdx.x * 16 + nl;
    int view = c / 12, chunk = c - view * 12;

    float part = 0.f;
    if (n < NN) {
        int b = g_off[n], e = g_off[n + 1];
        float acc[8];
        spmm_gather(g_B2h, (size_t)view * HH + chunk * 8, b, e, acc);
        float nin = rsqrtf((float)max(g_deg_in[n], 1));
        #pragma unroll
        for (int t = 0; t < 8; t++) {
            int j = chunk * 8 + t;
            float h = fmaf(acc[t], nin, sb2[j]);
            h = (h >= 0.f) ? h : sa2[j] * h;
            part = fmaf(h, swm[j], part);
        }
    }
    sp[threadIdx.x] = part;
    __syncthreads();

    if (threadIdx.x < 32) {
        int nl2 = threadIdx.x >> 1, vw = threadIdx.x & 1;
        int n2 = blockIdx.x * 16 + nl2;
        if (n2 < NN) {
            float s = g_bmsum;
            #pragma unroll
            for (int k = 0; k < 12; k++) s += sp[nl2 * 24 + vw * 12 + k];
            out[(size_t)vw * NN + n2] = s;
        }
    }
}

// ---------------- launch ----------------------------------------------------
extern "C" void kernel_launch(void* const* d_in, const int* in_sizes, int n_in,
                              void* d_out, int out_size) {
    const float* x    = (const float*)d_in[0];
    const int*   src  = (const int*)  d_in[1];
    const int*   dst  = (const int*)  d_in[2];
    const int*   perm = (const int*)  d_in[3];
    const float* W1   = (const float*)d_in[4];
    const float* b1   = (const float*)d_in[5];
    const float* a1   = (const float*)d_in[6];
    const float* W2   = (const float*)d_in[7];
    const float* b2   = (const float*)d_in[8];
    const float* a2   = (const float*)d_in[9];
    const float* Wm   = (const float*)d_in[10];
    const float* bm   = (const float*)d_in[11];
    float* out = (float*)d_out;

    __half *pB0h, *pB2h;
    __nv_bfloat16 *pW1h, *pW1l, *pW2h, *pW2l;
    int *pDegOut, *pDegIn, *pSync;
    cudaGetSymbolAddress((void**)&pB0h, g_B0h);
    cudaGetSymbolAddress((void**)&pB2h, g_B2h);
    cudaGetSymbolAddress((void**)&pW1h, g_W1t_h);
    cudaGetSymbolAddress((void**)&pW1l, g_W1t_l);
    cudaGetSymbolAddress((void**)&pW2h, g_W2t_h);
    cudaGetSymbolAddress((void**)&pW2l, g_W2t_l);
    cudaGetSymbolAddress((void**)&pDegOut, g_deg_out);
    cudaGetSymbolAddress((void**)&pDegIn,  g_deg_in);
    cudaGetSymbolAddress((void**)&pSync,   g_scan_sync);

    static cudaStream_t sB = nullptr, sC = nullptr, sD = nullptr;
    static cudaEvent_t evF, evDeg, evY, evCSR, evW2, evT;
    if (!sB) {
        cudaStreamCreateWithFlags(&sB, cudaStreamNonBlocking);
        cudaStreamCreateWithFlags(&sC, cudaStreamNonBlocking);
        cudaStreamCreateWithFlags(&sD, cudaStreamNonBlocking);
        cudaEventCreateWithFlags(&evF,   cudaEventDisableTiming);
        cudaEventCreateWithFlags(&evDeg, cudaEventDisableTiming);
        cudaEventCreateWithFlags(&evY,   cudaEventDisableTiming);
        cudaEventCreateWithFlags(&evCSR, cudaEventDisableTiming);
        cudaEventCreateWithFlags(&evW2,  cudaEventDisableTiming);
        cudaEventCreateWithFlags(&evT,   cudaEventDisableTiming);
        cudaFuncSetAttribute(k_gemm_mma<16, FIN, FIN, 512, NN, false, true>,
                             cudaFuncAttributeMaxDynamicSharedMemorySize, GEMM_SMEM);
        cudaFuncSetAttribute(k_gemm_mma<3, HH, HH, 128, 2 * NN, true, false>,
                             cudaFuncAttributeMaxDynamicSharedMemorySize, GEMM_SMEM);
    }

    const int GN  = (NN + 255) / 256;
    const int GE  = (EE + 255) / 256;
    const int GS  = (NN + 15) / 16;
    const int GT1 = (NN + 127) / 128;
    const int GT2 = (2 * NN + 127) / 128;

    // fork
    cudaEventRecord(evF, 0);
    cudaStreamWaitEvent(sB, evF, 0);
    cudaStreamWaitEvent(sC, evF, 0);
    cudaStreamWaitEvent(sD, evF, 0);

    // memsets
    cudaMemsetAsync(pDegIn,  0, NN * sizeof(int), sB);
    cudaMemsetAsync(pSync,   0, 2 * sizeof(int),  sB);
    cudaMemsetAsync(pDegOut, 0, NN * sizeof(int), sC);

    // kernel #1: W1 prep (main)
    k_wprep1<<<(HH * 512 + 255) / 256, 256>>>(W1);
    // kernels #2-3: iperm + count_out (sC)
    k_iperm<<<GN, 256, 0, sC>>>(perm);
    k_count_out<<<GE, 256, 0, sC>>>(src);
    cudaEventRecord(evDeg, sC);

    // kernel #4: GEMM1 (main) -- profiled launch
    cudaStreamWaitEvent(0, evDeg, 0);
    k_gemm_mma<16, FIN, FIN, 512, NN, false, true>
        <<<GT1, 256, GEMM_SMEM>>>(x, pW1h, pW1l, pB0h /*unused*/);
    cudaEventRecord(evY, 0);

    // kernels #5-7: CSR build (sB)
    k_count_in<<<GE, 256, 0, sB>>>(dst);
    k_scan_fused<<<NB, 256, 0, sB>>>();
    k_scatter<<<GE, 256, 0, sB>>>(src, dst);
    cudaEventRecord(evCSR, sB);

    // kernel #8: W2 prep + wmsum (sC, hidden)
    k_wprep2<<<(HH * 128 + 255) / 256, 256, 0, sC>>>(W2, Wm, bm);
    cudaEventRecord(evW2, sC);

    // kernels #9-10: spmm1 -> GEMM2 (sD)
    cudaStreamWaitEvent(sD, evY, 0);
    cudaStreamWaitEvent(sD, evCSR, 0);
    k_spmm1<<<GS, 384, 0, sD>>>(b1, a1);
    cudaStreamWaitEvent(sD, evW2, 0);
    k_gemm_mma<3, HH, HH, 128, 2 * NN, true, false>
        <<<GT2, 256, GEMM_SMEM, sD>>>(pB0h, pW2h, pW2l, pB2h);
    cudaEventRecord(evT, sD);

    // kernel #11: spmm2 (main = capture stream, graph leaf)
    cudaStreamWaitEvent(0, evT, 0);
    k_spmm2<<<GS, 384>>>(b2, a2, out);
}

// round 17
// speedup vs baseline: 1.1823x; 1.1277x over previous
#include <cuda_runtime.h>
#include <cuda_bf16.h>
#include <cuda_fp16.h>
#include <cstdint>

#define NN 50000
#define EE 800000
#define FIN 500
#define HH 96
#define NB 196        // scan blocks: ceil(NN/256)

// ---------------- scratch (device globals; no allocation allowed) ----------
__device__ int    g_deg_out[NN];
__device__ int    g_deg_in[NN];
__device__ int    g_iperm[NN];
__device__ int    g_off[NN + 1];
__device__ int    g_cur[NN];
__device__ int    g_bsum[NB];
__device__ int    g_boff[NB];
__device__ int    g_scan_sync[2];        // [0]=ticket, [1]=release flag
__device__ int    g_csr[EE];             // src per CSR slot
__device__ __half g_Y01[NN * 2 * HH];    // [norm_out*Y | norm_out*Y[perm]] per node
__device__ __half g_B0h[2 * NN * HH];    // layer-1 out, row n=2i+v, fp16
__device__ __half g_B2h[2 * NN * HH];    // B0 @ W2, row n=2i+v, fp16
__device__ float  g_wmsum[HH];
__device__ float  g_bmsum;
// transposed (n-major, k-contiguous), zero-padded, fp16 hi/lo weight copies
__device__ __half g_W1t_h[HH * 512];
__device__ __half g_W1t_l[HH * 512];
__device__ __half g_W2t_h[HH * 128];
__device__ __half g_W2t_l[HH * 128];

// ---------------- helpers ----------------------------------------------------
// pack two fp32 into fp16x2 bits (x -> lo, y -> hi)
__device__ __forceinline__ uint32_t pack_f16x2(float x, float y) {
    uint32_t r;
    asm("cvt.rn.f16x2.f32 %0, %1, %2;" : "=r"(r) : "f"(y), "f"(x));
    return r;
}

// fp16 MMA: D(f32) += A(f16,row) * B(f16,col)
__device__ __forceinline__ void mma16816(float* c, uint32_t a0, uint32_t a1,
                                         uint32_t a2, uint32_t a3,
                                         uint32_t b0, uint32_t b1) {
    asm volatile(
        "mma.sync.aligned.m16n8k16.row.col.f32.f16.f16.f32 "
        "{%0,%1,%2,%3}, {%4,%5,%6,%7}, {%8,%9}, {%0,%1,%2,%3};"
        : "+f"(c[0]), "+f"(c[1]), "+f"(c[2]), "+f"(c[3])
        : "r"(a0), "r"(a1), "r"(a2), "r"(a3), "r"(b0), "r"(b1));
}

// 256-thread block inclusive scan
__device__ __forceinline__ int block_scan256(int v, int tid) {
    int lane = tid & 31, wid = tid >> 5;
    int inc = v;
    #pragma unroll
    for (int o = 1; o < 32; o <<= 1) {
        int u = __shfl_up_sync(0xffffffffu, inc, o);
        if (lane >= o) inc += u;
    }
    __shared__ int ws[8];
    if (lane == 31) ws[wid] = inc;
    __syncthreads();
    if (wid == 0) {
        int w = (lane < 8) ? ws[lane] : 0;
        #pragma unroll
        for (int o = 1; o < 8; o <<= 1) {
            int u = __shfl_up_sync(0xffffffffu, w, o);
            if (lane >= o) w += u;
        }
        if (lane < 8) ws[lane] = w;
    }
    __syncthreads();
    return inc + (wid ? ws[wid - 1] : 0);
}

// ---------------- setup kernels --------------------------------------------
__global__ void k_iperm(const int* __restrict__ perm) {
    int i = blockIdx.x * blockDim.x + threadIdx.x;
    if (i < NN) g_iperm[perm[i]] = i;
}

__global__ void k_count_out(const int* __restrict__ src) {
    int e = blockIdx.x * blockDim.x + threadIdx.x;
    if (e < EE) atomicAdd(&g_deg_out[src[e]], 1);
}

__global__ void k_count_in(const int* __restrict__ dst) {
    int e = blockIdx.x * blockDim.x + threadIdx.x;
    if (e < EE) atomicAdd(&g_deg_in[dst[e]], 1);
}

// single-launch chained scan of g_deg_in -> g_off/g_cur (exclusive)
__global__ void k_scan_fused() {
    int tid = threadIdx.x;
    int i = blockIdx.x * 256 + tid;
    int v = (i < NN) ? g_deg_in[i] : 0;
    int inc = block_scan256(v, tid);

    __shared__ bool last;
    if (tid == 255) {
        g_bsum[blockIdx.x] = inc;
        __threadfence();
        last = (atomicAdd(&g_scan_sync[0], 1) == NB - 1);
    }
    __syncthreads();

    if (last) {
        int bv = (tid < NB) ? g_bsum[tid] : 0;
        int binc = block_scan256(bv, tid);
        if (tid < NB) g_boff[tid] = binc - bv;
        if (tid == 0) {
            g_off[NN] = EE;
            __threadfence();
            *(volatile int*)&g_scan_sync[1] = 1;
        }
    }

    __shared__ int base;
    if (tid == 0) {
        while (*(volatile int*)&g_scan_sync[1] == 0) { }
        base = g_boff[blockIdx.x];
    }
    __syncthreads();
    int run = base + inc - v;
    if (i < NN) { g_off[i] = run; g_cur[i] = run; }
}

__global__ void k_scatter(const int* __restrict__ src, const int* __restrict__ dst) {
    int e = blockIdx.x * blockDim.x + threadIdx.x;
    if (e < EE) {
        int p = atomicAdd(&g_cur[dst[e]], 1);
        g_csr[p] = src[e];
    }
}

__global__ void k_wprep1(const float* __restrict__ W1) {
    int idx = blockIdx.x * blockDim.x + threadIdx.x;
    if (idx < HH * 512) {
        int j = idx >> 9, k = idx & 511;
        float v = (k < FIN) ? W1[k * HH + j] : 0.f;
        __half h = __float2half_rn(v);
        g_W1t_h[idx] = h;
        g_W1t_l[idx] = __float2half_rn(v - __half2float(h));
    }
}

__global__ void k_wprep2(const float* __restrict__ W2,
                         const float* __restrict__ Wm, const float* __restrict__ bm) {
    int idx = blockIdx.x * blockDim.x + threadIdx.x;
    if (idx < HH * 128) {
        int j = idx >> 7, k = idx & 127;
        float v = (k < HH) ? W2[k * HH + j] : 0.f;
        __half h = __float2half_rn(v);
        g_W2t_h[idx] = h;
        g_W2t_l[idx] = __float2half_rn(v - __half2float(h));
    }
    if (blockIdx.x == 0 && threadIdx.x < HH) {
        int k = threadIdx.x;
        float s = 0.f;
        for (int j = 0; j < HH; j++) s += Wm[k * HH + j];
        g_wmsum[k] = s;
        if (k == 0) {
            float sb = 0.f;
            for (int j = 0; j < HH; j++) sb += bm[j];
            g_bmsum = sb;
        }
    }
}

// ---------------- tensor-core GEMM via mma.sync (fp16, 2-pass) --------------
// CTA: 128 rows x 96 cols, 8 warps as 4(m) x 2(n); warp = 2 m16 bands x 6 n8.
// K chunks of 32 (2 x k16). A fp16 (unsplit); W split fp16 hi/lo:
//   D = A*Wh + A*Wl   (2 passes, 24 HMMA / k16)
// SMEM row stride 20 words: banks 20*qr+qc cover all 32 -> conflict-free.
#define AW2 2560              // 128*20 words
#define BW2 1920              // 96*20 words
#define GEMM_SMEM ((2 * AW2 + 4 * BW2) * 4)   // 51200 bytes

template <int KCHUNKS, int KREAL, int LDA, int WLD, int NROWS, bool HALF_IN, bool EPI1>
__global__ void __launch_bounds__(256, 2)
k_gemm_mma(const void* __restrict__ Ain,
           const __half* __restrict__ Wh,
           const __half* __restrict__ Wl,
           __half* __restrict__ C) {
    extern __shared__ uint32_t dyn[];
    uint32_t* const AB[2]  = { dyn,            dyn + AW2 };
    uint32_t* const bbase  = dyn + 2 * AW2;
    uint32_t* const BhB[2] = { bbase,          bbase + 2 * BW2 };
    uint32_t* const BlB[2] = { bbase + BW2,    bbase + 3 * BW2 };

    int tid = threadIdx.x, wid = tid >> 5, lane = tid & 31;
    int mw = wid >> 1, nw = wid & 1;
    int r0 = blockIdx.x * 128;

    float acc[2][6][4];
    #pragma unroll
    for (int b = 0; b < 2; b++)
        #pragma unroll
        for (int t = 0; t < 6; t++)
            #pragma unroll
            for (int j = 0; j < 4; j++) acc[b][t][j] = 0.f;

    const int qr = lane >> 2, qc = lane & 3;

    float4   va4[4];     // fp32 A path
    uint4    vah[2];     // fp16 A path
    uint32_t vbh[6], vbl[6];

    #define LOAD_CHUNK(cc)                                                     \
    {                                                                          \
        int kbase = (cc) * 32;                                                 \
        if (HALF_IN) {                                                         \
            _Pragma("unroll")                                                  \
            for (int it = 0; it < 2; it++) {                                   \
                int idx = tid + it * 256;                                      \
                int r = idx >> 2, q = idx & 3;                                 \
                int gr = r0 + r;                                               \
                uint4 v = make_uint4(0u, 0u, 0u, 0u);                          \
                if (gr < NROWS)                                                \
                    v = *(const uint4*)((const __half*)Ain +                   \
                            (size_t)gr * LDA + kbase + 8 * q);                 \
                vah[it] = v;                                                   \
            }                                                                  \
        } else {                                                               \
            int kvq = (KREAL - kbase + 3) >> 2;                                \
            if (kvq > 8) kvq = 8;                                              \
            _Pragma("unroll")                                                  \
            for (int it = 0; it < 4; it++) {                                   \
                int idx = tid + it * 256;                                      \
                int r = idx >> 3, q = idx & 7;                                 \
                int gr = r0 + r;                                               \
                float4 v = make_float4(0.f, 0.f, 0.f, 0.f);                    \
                if (gr < NROWS && q < kvq)                                     \
                    v = *(const float4*)((const float*)Ain +                   \
                            (size_t)gr * LDA + kbase + 4 * q);                 \
                va4[it] = v;                                                   \
            }                                                                  \
        }                                                                      \
        _Pragma("unroll")                                                      \
        for (int it = 0; it < 6; it++) {                                       \
            int idx = tid + it * 256;                                          \
            int n = idx >> 4, kp = idx & 15;                                   \
            vbh[it] = *(const uint32_t*)(Wh + (size_t)n * WLD + kbase + 2 * kp);\
            vbl[it] = *(const uint32_t*)(Wl + (size_t)n * WLD + kbase + 2 * kp);\
        }                                                                      \
    }

    #define STORE_CHUNK(buf)                                                   \
    {                                                                          \
        if (HALF_IN) {                                                         \
            _Pragma("unroll")                                                  \
            for (int it = 0; it < 2; it++) {                                   \
                int idx = tid + it * 256;                                      \
                int r = idx >> 2, q = idx & 3;                                 \
                *(uint4*)&AB[buf][r * 20 + 4 * q] = vah[it];                   \
            }                                                                  \
        } else {                                                               \
            _Pragma("unroll")                                                  \
            for (int it = 0; it < 4; it++) {                                   \
                int idx = tid + it * 256;                                      \
                int r = idx >> 3, q = idx & 7;                                 \
                float4 v = va4[it];                                            \
                uint2 p;                                                       \
                p.x = pack_f16x2(v.x, v.y);                                    \
                p.y = pack_f16x2(v.z, v.w);                                    \
                *(uint2*)&AB[buf][r * 20 + 2 * q] = p;                         \
            }                                                                  \
        }                                                                      \
        _Pragma("unroll")                                                      \
        for (int it = 0; it < 6; it++) {                                       \
            int idx = tid + it * 256;                                          \
            int n = idx >> 4, kp = idx & 15;                                   \
            BhB[buf][n * 20 + kp] = vbh[it];                                   \
            BlB[buf][n * 20 + kp] = vbl[it];                                   \
        }                                                                      \
    }

    LOAD_CHUNK(0);
    STORE_CHUNK(0);
    __syncthreads();

    for (int c = 0; c < KCHUNKS; c++) {
        if (c + 1 < KCHUNKS) LOAD_CHUNK(c + 1);

        const uint32_t* sA  = AB[c & 1];
        const uint32_t* sBh = BhB[c & 1];
        const uint32_t* sBl = BlB[c & 1];

        #pragma unroll
        for (int s = 0; s < 2; s++) {
            int kq = s * 8 + qc;
            uint32_t bh[6][2], bl[6][2];
            #pragma unroll
            for (int t = 0; t < 6; t++) {
                int bc = nw * 48 + t * 8 + qr;
                bh[t][0] = sBh[bc * 20 + kq]; bh[t][1] = sBh[bc * 20 + kq + 4];
                bl[t][0] = sBl[bc * 20 + kq]; bl[t][1] = sBl[bc * 20 + kq + 4];
            }
            uint32_t a[2][4];
            #pragma unroll
            for (int b = 0; b < 2; b++) {
                int ar = mw * 32 + b * 16 + qr;
                a[b][0] = sA[ar * 20 + kq];     a[b][1] = sA[(ar + 8) * 20 + kq];
                a[b][2] = sA[ar * 20 + kq + 4]; a[b][3] = sA[(ar + 8) * 20 + kq + 4];
            }
            // 2 passes (Wh, Wl), pass-outer for accumulator independence
            #pragma unroll
            for (int p = 0; p < 2; p++) {
                #pragma unroll
                for (int b = 0; b < 2; b++) {
                    #pragma unroll
                    for (int t = 0; t < 6; t++) {
                        const uint32_t* bb = p ? bl[t] : bh[t];
                        mma16816(acc[b][t], a[b][0], a[b][1], a[b][2], a[b][3],
                                 bb[0], bb[1]);
                    }
                }
            }
        }

        if (c + 1 < KCHUNKS) {
            STORE_CHUNK((c + 1) & 1);
            __syncthreads();
        }
    }

    if (EPI1) {
        #pragma unroll
        for (int b = 0; b < 2; b++)
            #pragma unroll
            for (int h = 0; h < 2; h++) {
                int row = r0 + mw * 32 + b * 16 + qr + h * 8;
                if (row < NROWS) {
                    float no1 = rsqrtf((float)max(g_deg_out[row], 1));
                    int   n2  = g_iperm[row];
                    float no2 = rsqrtf((float)max(g_deg_out[n2], 1));
                    #pragma unroll
                    for (int t = 0; t < 6; t++) {
                        int col = nw * 48 + t * 8 + 2 * qc;
                        float vx = acc[b][t][2 * h], vy = acc[b][t][2 * h + 1];
                        *(uint32_t*)(g_Y01 + (size_t)row * (2 * HH) + col) =
                            pack_f16x2(no1 * vx, no1 * vy);
                        *(uint32_t*)(g_Y01 + (size_t)n2 * (2 * HH) + HH + col) =
                            pack_f16x2(no2 * vx, no2 * vy);
                    }
                }
            }
    } else {
        #pragma unroll
        for (int b = 0; b < 2; b++)
            #pragma unroll
            for (int t = 0; t < 6; t++) {
                int col = nw * 48 + t * 8 + 2 * qc;
                #pragma unroll
                for (int h = 0; h < 2; h++) {
                    int row = r0 + mw * 32 + b * 16 + qr + h * 8;
                    if (row < NROWS)
                        *(uint32_t*)(C + (size_t)row * HH + col) =
                            pack_f16x2(acc[b][t][2 * h], acc[b][t][2 * h + 1]);
                }
            }
    }
    #undef LOAD_CHUNK
    #undef STORE_CHUNK
}

// ---------------- SpMM gather core: 8x unrolled, 16B/lane -------------------
__device__ __forceinline__ void spmm_gather(const __half* __restrict__ base,
                                            size_t loff, int b, int e,
                                            float* acc) {
    #pragma unroll
    for (int t = 0; t < 8; t++) acc[t] = 0.f;
    auto addv = [&](uint4 v) {
        __half2* h2 = (__half2*)&v;
        #pragma unroll
        for (int t = 0; t < 4; t++) {
            float2 f = __half22float2(h2[t]);
            acc[2 * t]     += f.x;
            acc[2 * t + 1] += f.y;
        }
    };
    int p = b;
    for (; p + 8 <= e; p += 8) {
        int s[8];
        #pragma unroll
        for (int u = 0; u < 8; u++) s[u] = g_csr[p + u];
        uint4 v[8];
        #pragma unroll
        for (int u = 0; u < 8; u++)
            v[u] = *(const uint4*)(base + (size_t)s[u] * (2 * HH) + loff);
        #pragma unroll
        for (int u = 0; u < 8; u++) addv(v[u]);
    }
    for (; p + 2 <= e; p += 2) {
        int s0 = g_csr[p], s1 = g_csr[p + 1];
        uint4 v0 = *(const uint4*)(base + (size_t)s0 * (2 * HH) + loff);
        uint4 v1 = *(const uint4*)(base + (size_t)s1 * (2 * HH) + loff);
        addv(v0); addv(v1);
    }
    if (p < e)
        addv(*(const uint4*)(base + (size_t)g_csr[p] * (2 * HH) + loff));
}

// ---------------- fused SpMM layer 1: thread = (node, 24-chunk) -------------
__global__ void __launch_bounds__(384)
k_spmm1(const float* __restrict__ b1, const float* __restrict__ a1) {
    __shared__ float sb1[HH], sa1[HH];
    for (int j = threadIdx.x; j < HH; j += blockDim.x) {
        sb1[j] = b1[j];
        sa1[j] = a1[j];
    }
    __syncthreads();

    int nl = threadIdx.x / 24, c = threadIdx.x - nl * 24;
    int n = blockIdx.x * 16 + nl;
    if (n >= NN) return;
    int view = c / 12, chunk = c - view * 12;
    int b = g_off[n], e = g_off[n + 1];

    float acc[8];
    spmm_gather(g_Y01, (size_t)view * HH + chunk * 8, b, e, acc);

    float nin  = rsqrtf((float)max(g_deg_in[n], 1));
    float nout = rsqrtf((float)max(g_deg_out[n], 1));
    uint4 o;
    uint32_t* ow = (uint32_t*)&o;
    #pragma unroll
    for (int q = 0; q < 4; q++) {
        float r[2];
        #pragma unroll
        for (int u = 0; u < 2; u++) {
            int j = chunk * 8 + 2 * q + u;
            float h = fmaf(acc[2 * q + u], nin, sb1[j]);
            h = (h >= 0.f) ? h : sa1[j] * h;
            r[u] = nout * h;
        }
        ow[q] = pack_f16x2(r[0], r[1]);
    }
    *(uint4*)(g_B0h + ((size_t)(2 * n + view)) * HH + chunk * 8) = o;
}

// ---------------- fused SpMM layer 2 + readout: 24-thread groups ------------
__global__ void __launch_bounds__(384)
k_spmm2(const float* __restrict__ b2, const float* __restrict__ a2,
        float* __restrict__ out) {
    __shared__ float sb2[HH], sa2[HH], swm[HH], sp[384];
    for (int j = threadIdx.x; j < HH; j += blockDim.x) {
        sb2[j] = b2[j];
        sa2[j] = a2[j];
        swm[j] = g_wmsum[j];
    }
    __syncthreads();

    int nl = threadIdx.x / 24, c = threadIdx.x - nl * 24;
    int n = blockIdx.x * 16 + nl;
    int view = c / 12, chunk = c - view * 12;

    float part = 0.f;
    if (n < NN) {
        int b = g_off[n], e = g_off[n + 1];
        float acc[8];
        spmm_gather(g_B2h, (size_t)view * HH + chunk * 8, b, e, acc);
        float nin = rsqrtf((float)max(g_deg_in[n], 1));
        #pragma unroll
        for (int t = 0; t < 8; t++) {
            int j = chunk * 8 + t;
            float h = fmaf(acc[t], nin, sb2[j]);
            h = (h >= 0.f) ? h : sa2[j] * h;
            part = fmaf(h, swm[j], part);
        }
    }
    sp[threadIdx.x] = part;
    __syncthreads();

    if (threadIdx.x < 32) {
        int nl2 = threadIdx.x >> 1, vw = threadIdx.x & 1;
        int n2 = blockIdx.x * 16 + nl2;
        if (n2 < NN) {
            float s = g_bmsum;
            #pragma unroll
            for (int k = 0; k < 12; k++) s += sp[nl2 * 24 + vw * 12 + k];
            out[(size_t)vw * NN + n2] = s;
        }
    }
}

// ---------------- launch ----------------------------------------------------
extern "C" void kernel_launch(void* const* d_in, const int* in_sizes, int n_in,
                              void* d_out, int out_size) {
    const float* x    = (const float*)d_in[0];
    const int*   src  = (const int*)  d_in[1];
    const int*   dst  = (const int*)  d_in[2];
    const int*   perm = (const int*)  d_in[3];
    const float* W1   = (const float*)d_in[4];
    const float* b1   = (const float*)d_in[5];
    const float* a1   = (const float*)d_in[6];
    const float* W2   = (const float*)d_in[7];
    const float* b2   = (const float*)d_in[8];
    const float* a2   = (const float*)d_in[9];
    const float* Wm   = (const float*)d_in[10];
    const float* bm   = (const float*)d_in[11];
    float* out = (float*)d_out;

    __half *pB0h, *pB2h, *pW1h, *pW1l, *pW2h, *pW2l;
    int *pDegOut, *pDegIn, *pSync;
    cudaGetSymbolAddress((void**)&pB0h, g_B0h);
    cudaGetSymbolAddress((void**)&pB2h, g_B2h);
    cudaGetSymbolAddress((void**)&pW1h, g_W1t_h);
    cudaGetSymbolAddress((void**)&pW1l, g_W1t_l);
    cudaGetSymbolAddress((void**)&pW2h, g_W2t_h);
    cudaGetSymbolAddress((void**)&pW2l, g_W2t_l);
    cudaGetSymbolAddress((void**)&pDegOut, g_deg_out);
    cudaGetSymbolAddress((void**)&pDegIn,  g_deg_in);
    cudaGetSymbolAddress((void**)&pSync,   g_scan_sync);

    static cudaStream_t sB = nullptr, sC = nullptr, sD = nullptr;
    static cudaEvent_t evF, evDeg, evY, evCSR, evW2, evT;
    if (!sB) {
        cudaStreamCreateWithFlags(&sB, cudaStreamNonBlocking);
        cudaStreamCreateWithFlags(&sC, cudaStreamNonBlocking);
        cudaStreamCreateWithFlags(&sD, cudaStreamNonBlocking);
        cudaEventCreateWithFlags(&evF,   cudaEventDisableTiming);
        cudaEventCreateWithFlags(&evDeg, cudaEventDisableTiming);
        cudaEventCreateWithFlags(&evY,   cudaEventDisableTiming);
        cudaEventCreateWithFlags(&evCSR, cudaEventDisableTiming);
        cudaEventCreateWithFlags(&evW2,  cudaEventDisableTiming);
        cudaEventCreateWithFlags(&evT,   cudaEventDisableTiming);
        cudaFuncSetAttribute(k_gemm_mma<16, FIN, FIN, 512, NN, false, true>,
                             cudaFuncAttributeMaxDynamicSharedMemorySize, GEMM_SMEM);
        cudaFuncSetAttribute(k_gemm_mma<3, HH, HH, 128, 2 * NN, true, false>,
                             cudaFuncAttributeMaxDynamicSharedMemorySize, GEMM_SMEM);
    }

    const int GN  = (NN + 255) / 256;
    const int GE  = (EE + 255) / 256;
    const int GS  = (NN + 15) / 16;
    const int GT1 = (NN + 127) / 128;
    const int GT2 = (2 * NN + 127) / 128;

    // fork
    cudaEventRecord(evF, 0);
    cudaStreamWaitEvent(sB, evF, 0);
    cudaStreamWaitEvent(sC, evF, 0);
    cudaStreamWaitEvent(sD, evF, 0);

    // memsets
    cudaMemsetAsync(pDegIn,  0, NN * sizeof(int), sB);
    cudaMemsetAsync(pSync,   0, 2 * sizeof(int),  sB);
    cudaMemsetAsync(pDegOut, 0, NN * sizeof(int), sC);

    // kernel #1: W1 prep (main)
    k_wprep1<<<(HH * 512 + 255) / 256, 256>>>(W1);
    // kernels #2-3: iperm + count_out (sC)
    k_iperm<<<GN, 256, 0, sC>>>(perm);
    k_count_out<<<GE, 256, 0, sC>>>(src);
    cudaEventRecord(evDeg, sC);

    // kernel #4: GEMM1 (main) -- profiled launch
    cudaStreamWaitEvent(0, evDeg, 0);
    k_gemm_mma<16, FIN, FIN, 512, NN, false, true>
        <<<GT1, 256, GEMM_SMEM>>>(x, pW1h, pW1l, pB0h /*unused*/);
    cudaEventRecord(evY, 0);

    // kernels #5-7: CSR build (sB)
    k_count_in<<<GE, 256, 0, sB>>>(dst);
    k_scan_fused<<<NB, 256, 0, sB>>>();
    k_scatter<<<GE, 256, 0, sB>>>(src, dst);
    cudaEventRecord(evCSR, sB);

    // kernel #8: W2 prep + wmsum (sC, hidden)
    k_wprep2<<<(HH * 128 + 255) / 256, 256, 0, sC>>>(W2, Wm, bm);
    cudaEventRecord(evW2, sC);

    // kernels #9-10: spmm1 -> GEMM2 (sD)
    cudaStreamWaitEvent(sD, evY, 0);
    cudaStreamWaitEvent(sD, evCSR, 0);
    k_spmm1<<<GS, 384, 0, sD>>>(b1, a1);
    cudaStreamWaitEvent(sD, evW2, 0);
    k_gemm_mma<3, HH, HH, 128, 2 * NN, true, false>
        <<<GT2, 256, GEMM_SMEM, sD>>>(pB0h, pW2h, pW2l, pB2h);
    cudaEventRecord(evT, sD);

    // kernel #11: spmm2 (main = capture stream, graph leaf)
    cudaStreamWaitEvent(0, evT, 0);
    k_spmm2<<<GS, 384>>>(b2, a2, out);
}